// round 2
// baseline (speedup 1.0000x reference)
#include <cuda_runtime.h>
#include <cuda_bf16.h>
#include <math.h>

// ---------------- problem constants ----------------
#define NB    32          // batch
#define NT    32          // decode steps (TRG-1)
#define NH    512         // hidden = emb
#define NSRC  400
#define NV    32000
#define NVEXT 32050
#define NK3   1536        // 3*H
#define NG4   2048        // 4*H
#define VPAD  32256       // NV padded to multiple of 512 for the GEMM
#define ATTN_SCALE 0.04419417382415922f   // 1/sqrt(512)
#define RESCORE_MARGIN 1.5e-3f
#define MAXCAND 64

typedef unsigned long long ull;

// ---------------- device scratch (static, no allocs) ----------------
__device__ float g_WT_ih[512 * 2048];          // [k][j]
__device__ float g_WT_hh[512 * 2048];          // [k][j]
__device__ __nv_bfloat16 g_WTv[1536 * VPAD];   // [k][v], bf16, padded
__device__ float g_h[NB * NH];
__device__ float g_c[NB * NH];
__device__ float g_buf[NB * NT * NH];          // decoder state buffer
__device__ float g_gpart[4 * NB * NG4];        // k-split partial gates
__device__ float g_q[NB * NH];                 // h @ W_attn
__device__ float g_feat[NB * NK3];             // [h, ed_ctx, ds_ctx]
__device__ float g_aw[NB * NSRC];              // attention weights (for copy)
__device__ float g_p[NB];                      // copy gate

// ---------------- small helpers ----------------
__device__ __forceinline__ float warp_sum(float v) {
    #pragma unroll
    for (int o = 16; o; o >>= 1) v += __shfl_xor_sync(0xffffffffu, v, o);
    return v;
}
__device__ __forceinline__ float warp_max(float v) {
    #pragma unroll
    for (int o = 16; o; o >>= 1) v = fmaxf(v, __shfl_xor_sync(0xffffffffu, v, o));
    return v;
}
__device__ __forceinline__ float sigmoidf_(float x) { return 1.0f / (1.0f + expf(-x)); }

// ---------------- init kernels ----------------
__global__ void k_init_state(const float* __restrict__ h0, const float* __restrict__ c0) {
    int i = blockIdx.x * 256 + threadIdx.x;
    if (i < NB * NH) { g_h[i] = h0[i]; g_c[i] = c0[i]; }
}

__global__ void k_transpose_small(const float* __restrict__ W_ih, const float* __restrict__ W_hh) {
    int i = blockIdx.x * 256 + threadIdx.x;
    if (i < 2048 * 512) {
        int j = i >> 9, k = i & 511;
        g_WT_ih[k * 2048 + j] = W_ih[i];
        g_WT_hh[k * 2048 + j] = W_hh[i];
    }
}

// tiled transpose + bf16 convert: W_vocab[v][k] -> g_WTv[k][v] (v padded with 0)
__global__ void k_transpose_vocab(const float* __restrict__ W_vocab) {
    __shared__ float t[32][33];
    int tx = threadIdx.x, ty = threadIdx.y;          // block (32, 8)
    int vt = blockIdx.x * 32, kt = blockIdx.y * 32;
    #pragma unroll
    for (int r = 0; r < 4; r++) {
        int v_in = vt + ty + 8 * r;
        int k_in = kt + tx;
        t[ty + 8 * r][tx] = (v_in < NV) ? W_vocab[v_in * NK3 + k_in] : 0.0f;
    }
    __syncthreads();
    #pragma unroll
    for (int r = 0; r < 4; r++) {
        int k_out = kt + ty + 8 * r;
        int v_out = vt + tx;
        g_WTv[k_out * VPAD + v_out] = __float2bfloat16(t[tx][ty + 8 * r]);
    }
}

// ---------------- step kernel 1: LSTM gates (k-split GEMM) ----------------
// grid (16 j-blocks, 2 b-halves, 4 k-quarters), block 128
__global__ void k_gates(const int* __restrict__ dec, const float* __restrict__ emb, int di) {
    __shared__ float xs[256][16];
    int tid = threadIdx.x;
    int j   = blockIdx.x * 128 + tid;
    int b0  = blockIdx.y * 16;
    int kq  = blockIdx.z;                 // 0,1: x-part   2,3: h-part
    int koff = (kq & 1) * 256;

    for (int idx = tid; idx < 256 * 16; idx += 128) {
        int kk = idx >> 4, bb = idx & 15;
        int b = b0 + bb;
        float v;
        if (kq < 2) {
            int tok = dec[b * (NT + 1) + di];
            if (tok >= NV) tok = 1;       // UNK
            v = emb[tok * NH + koff + kk];
        } else {
            v = g_h[b * NH + koff + kk];
        }
        xs[kk][bb] = v;
    }
    __syncthreads();

    const float* WT = (kq < 2) ? g_WT_ih : g_WT_hh;
    float acc[16];
    #pragma unroll
    for (int bb = 0; bb < 16; bb++) acc[bb] = 0.0f;

    for (int kk = 0; kk < 256; kk++) {
        float w = WT[(koff + kk) * NG4 + j];
        #pragma unroll
        for (int bb = 0; bb < 16; bb++) acc[bb] = fmaf(w, xs[kk][bb], acc[bb]);
    }
    #pragma unroll
    for (int bb = 0; bb < 16; bb++)
        g_gpart[((kq * NB) + b0 + bb) * NG4 + j] = acc[bb];
}

// ---------------- step kernel 2: LSTM cell update ----------------
__global__ void k_cell(const float* __restrict__ b_ih, const float* __restrict__ b_hh, int di) {
    int idx = blockIdx.x * 256 + threadIdx.x;     // 32*512
    if (idx >= NB * NH) return;
    int b = idx >> 9, hh = idx & 511;
    float vi = b_ih[hh]        + b_hh[hh];
    float vf = b_ih[512 + hh]  + b_hh[512 + hh];
    float vg = b_ih[1024 + hh] + b_hh[1024 + hh];
    float vo = b_ih[1536 + hh] + b_hh[1536 + hh];
    #pragma unroll
    for (int kq = 0; kq < 4; kq++) {
        const float* gp = &g_gpart[((kq * NB) + b) * NG4];
        vi += gp[hh]; vf += gp[512 + hh]; vg += gp[1024 + hh]; vo += gp[1536 + hh];
    }
    float c = sigmoidf_(vf) * g_c[idx] + sigmoidf_(vi) * tanhf(vg);
    float h = sigmoidf_(vo) * tanhf(c);
    g_c[idx] = c;
    g_h[idx] = h;
    g_buf[b * (NT * NH) + di * NH + hh] = h;   // safe: this step only reads t < di
}

// ---------------- step kernel 3: q = h @ W_attn ----------------
__global__ void k_q(const float* __restrict__ W_attn) {
    __shared__ float hs[512];
    int b = blockIdx.x;
    int e = blockIdx.y * 128 + threadIdx.x;
    for (int i = threadIdx.x; i < 512; i += 128) hs[i] = g_h[b * NH + i];
    __syncthreads();
    float acc = 0.0f;
    #pragma unroll 8
    for (int h = 0; h < 512; h++) acc = fmaf(hs[h], W_attn[h * NH + e], acc);
    g_q[b * NH + e] = acc;
}

// ---------------- step kernel 4: attention + feat + copy gate ----------------
__global__ void k_attn(const float* __restrict__ enc,
                       const float* __restrict__ W_copy,
                       const float* __restrict__ b_copy, int di) {
    __shared__ float qs[512], hs[512], sc[NSRC], ss[32], sw[32], red[8];
    int b = blockIdx.x, tid = threadIdx.x;
    int lane = tid & 31, wid = tid >> 5;
    const float* encb = enc + (size_t)b * NSRC * NH;

    for (int i = tid; i < 512; i += 256) { qs[i] = g_q[b * NH + i]; hs[i] = g_h[b * NH + i]; }
    __syncthreads();

    // encoder attention scores
    for (int s = wid; s < NSRC; s += 8) {
        float a = 0.0f;
        #pragma unroll 4
        for (int i = lane; i < 512; i += 32) a = fmaf(qs[i], encb[s * NH + i], a);
        a = warp_sum(a);
        if (lane == 0) sc[s] = a * ATTN_SCALE;
    }
    __syncthreads();

    // softmax over 400
    float m = -1e30f;
    for (int v = tid; v < NSRC; v += 256) m = fmaxf(m, sc[v]);
    m = warp_max(m);
    if (lane == 0) red[wid] = m;
    __syncthreads();
    if (tid == 0) { float t = red[0]; for (int i = 1; i < 8; i++) t = fmaxf(t, red[i]); red[0] = t; }
    __syncthreads();
    float gm = red[0];
    __syncthreads();
    float lsum = 0.0f;
    for (int v = tid; v < NSRC; v += 256) { float e = expf(sc[v] - gm); sc[v] = e; lsum += e; }
    lsum = warp_sum(lsum);
    if (lane == 0) red[wid] = lsum;
    __syncthreads();
    if (tid == 0) { float t = 0.f; for (int i = 0; i < 8; i++) t += red[i]; red[0] = t; }
    __syncthreads();
    float inv = 1.0f / red[0];
    for (int v = tid; v < NSRC; v += 256) { float a = sc[v] * inv; sc[v] = a; g_aw[b * NSRC + v] = a; }
    __syncthreads();

    // ed_ctx
    for (int h = tid; h < 512; h += 256) {
        float a = 0.0f;
        for (int s = 0; s < NSRC; s++) a = fmaf(sc[s], encb[s * NH + h], a);
        g_feat[b * NK3 + 512 + h] = a;
    }

    // intra-decoder attention
    if (di > 0) {
        const float* bufb = &g_buf[b * (NT * NH)];
        for (int t = wid; t < di; t += 8) {
            float a = 0.0f;
            #pragma unroll 4
            for (int i = lane; i < 512; i += 32) a = fmaf(hs[i], bufb[t * NH + i], a);
            a = warp_sum(a);
            if (lane == 0) ss[t] = a * ATTN_SCALE;
        }
        __syncthreads();
        if (tid < 32) {
            float v = (tid < di) ? ss[tid] : -1e30f;
            float mm = warp_max(v);
            float e = (tid < di) ? expf(v - mm) : 0.0f;
            float s = warp_sum(e);
            sw[tid] = (tid < di) ? e / s : 0.0f;
        }
        __syncthreads();
        for (int h = tid; h < 512; h += 256) {
            float a = 0.0f;
            for (int t = 0; t < di; t++) a = fmaf(sw[t], bufb[t * NH + h], a);
            g_feat[b * NK3 + 1024 + h] = a;
        }
    } else {
        for (int h = tid; h < 512; h += 256) g_feat[b * NK3 + 1024 + h] = 0.0f;
    }
    for (int h = tid; h < 512; h += 256) g_feat[b * NK3 + h] = hs[h];
    __syncthreads();

    // copy gate p
    float a = 0.0f;
    for (int k = tid; k < NK3; k += 256) a = fmaf(g_feat[b * NK3 + k], W_copy[k], a);
    a = warp_sum(a);
    if (lane == 0) red[wid] = a;
    __syncthreads();
    if (tid == 0) {
        float t = 0.f; for (int i = 0; i < 8; i++) t += red[i];
        g_p[b] = sigmoidf_(t + b_copy[0]);
    }
}

// ---------------- step kernel 5: vocab GEMM (fp32x2, bf16 weights) ----------------
// grid (126 v-blocks of 256, 2 b-halves), block 128. thread: 2 v (1 f32x2 pair) x 16 b
__global__ void __launch_bounds__(128) k_vocab(const float* __restrict__ b_vocab,
                                               float* __restrict__ out, int di) {
    __shared__ __align__(16) ull fs[16][132];   // [bb][kk], feat dup'd into both f32x2 lanes
    int tid = threadIdx.x;
    int v0 = blockIdx.x * 256 + tid * 2;
    int b0 = blockIdx.y * 16;

    ull acc[16];
    #pragma unroll
    for (int bb = 0; bb < 16; bb++) acc[bb] = 0ull;

    for (int kc = 0; kc < 12; kc++) {
        for (int idx = tid; idx < 128 * 16; idx += 128) {
            int bb = idx >> 7, kk = idx & 127;
            unsigned int fu = __float_as_uint(g_feat[(b0 + bb) * NK3 + kc * 128 + kk]);
            fs[bb][kk] = ((ull)fu << 32) | (ull)fu;
        }
        __syncthreads();
        const __nv_bfloat16* wrow = &g_WTv[(size_t)(kc * 128) * VPAD + v0];
        #pragma unroll 4
        for (int kk = 0; kk < 128; kk += 2) {
            unsigned int wu0 = *(const unsigned int*)(wrow + (size_t)kk * VPAD);
            unsigned int wu1 = *(const unsigned int*)(wrow + (size_t)(kk + 1) * VPAD);
            ull w0 = ((ull)(wu0 & 0xFFFF0000u) << 32) | ((ull)wu0 << 16);
            ull w1 = ((ull)(wu1 & 0xFFFF0000u) << 32) | ((ull)wu1 << 16);
            #pragma unroll
            for (int bb = 0; bb < 16; bb++) {
                ull f0 = fs[bb][kk];
                ull f1 = fs[bb][kk + 1];
                asm("fma.rn.f32x2 %0, %1, %2, %0;" : "+l"(acc[bb]) : "l"(w0), "l"(f0));
                asm("fma.rn.f32x2 %0, %1, %2, %0;" : "+l"(acc[bb]) : "l"(w1), "l"(f1));
            }
        }
        __syncthreads();
    }

    float bv0 = (v0 < NV)     ? b_vocab[v0]     : 0.0f;
    float bv1 = (v0 + 1 < NV) ? b_vocab[v0 + 1] : 0.0f;

    #pragma unroll
    for (int bb = 0; bb < 16; bb++) {
        int b = b0 + bb;
        float pm = 1.0f - g_p[b];
        float* row = out + ((size_t)(b * NT + di)) * NVEXT;
        float x0 = __uint_as_float((unsigned)(acc[bb] & 0xffffffffu));
        float x1 = __uint_as_float((unsigned)(acc[bb] >> 32));
        if (v0 < NV)              row[v0]     = (x0 + bv0) * pm;
        else if (v0 < NVEXT)      row[v0]     = 0.0f;
        if (v0 + 1 < NV)          row[v0 + 1] = (x1 + bv1) * pm;
        else if (v0 + 1 < NVEXT)  row[v0 + 1] = 0.0f;
    }
}

// ---------------- step kernel 6: copy scatter-add ----------------
__global__ void k_scatter(const int* __restrict__ ext, float* __restrict__ out, int di) {
    int idx = blockIdx.x * 256 + threadIdx.x;
    if (idx >= NB * NSRC) return;
    int b = idx / NSRC, s = idx - b * NSRC;
    float add = g_p[b] * g_aw[b * NSRC + s];
    atomicAdd(out + ((size_t)(b * NT + di)) * NVEXT + ext[b * NSRC + s], add);
}

// ---------------- step kernel 7: log-softmax ----------------
__global__ void k_logsm(float* __restrict__ out, int di) {
    __shared__ float sred[256];
    int b = blockIdx.x, tid = threadIdx.x;
    float* row = out + ((size_t)(b * NT + di)) * NVEXT;

    float m = -1e30f;
    for (int v = tid; v < NVEXT; v += 256) m = fmaxf(m, row[v]);
    sred[tid] = m;
    __syncthreads();
    for (int s = 128; s > 0; s >>= 1) {
        if (tid < s) sred[tid] = fmaxf(sred[tid], sred[tid + s]);
        __syncthreads();
    }
    float gm = sred[0];
    __syncthreads();

    float lsum = 0.0f;
    for (int v = tid; v < NVEXT; v += 256) lsum += expf(row[v] - gm);
    sred[tid] = lsum;
    __syncthreads();
    for (int s = 128; s > 0; s >>= 1) {
        if (tid < s) sred[tid] += sred[tid + s];
        __syncthreads();
    }
    float lz = gm + logf(sred[0]);

    for (int v = tid; v < NVEXT; v += 256) row[v] = row[v] - lz;
}

// ---------------- step kernel 8: exact-fp32 top-candidate rescore -> argmax ----------------
// The bf16 GEMM's logit noise (~4e-5 abs) is fine for logp (threshold 1e-3 rel on ~10.4
// magnitudes) but can flip argmax at tight top-2 gaps. Select all candidates within
// RESCORE_MARGIN of the row max, recompute each candidate's merged value exactly in fp32
// (gen dot + bias, *(1-p), + deterministic copy sum), argmax with first-index tie-break.
__global__ void k_rescore(const float* __restrict__ W_vocab,
                          const float* __restrict__ b_vocab,
                          const int* __restrict__ ext,
                          const float* __restrict__ out,
                          float* __restrict__ pred_out, int di) {
    __shared__ float redA[8], redC[8], sred[256];
    __shared__ int   cand[MAXCAND];
    __shared__ float cval[MAXCAND];
    __shared__ int   ccount;
    int b = blockIdx.x, tid = threadIdx.x;
    int lane = tid & 31, wid = tid >> 5;
    const float* row = out + ((size_t)(b * NT + di)) * NVEXT;

    // row max (of logp row; shift-invariant for selection)
    float m = -1e30f;
    for (int v = tid; v < NVEXT; v += 256) m = fmaxf(m, row[v]);
    sred[tid] = m;
    __syncthreads();
    for (int s = 128; s > 0; s >>= 1) {
        if (tid < s) sred[tid] = fmaxf(sred[tid], sred[tid + s]);
        __syncthreads();
    }
    float thr = sred[0] - RESCORE_MARGIN;
    if (tid == 0) ccount = 0;
    __syncthreads();

    for (int v = tid; v < NVEXT; v += 256) {
        if (row[v] >= thr) {
            int p = atomicAdd(&ccount, 1);
            if (p < MAXCAND) cand[p] = v;
        }
    }
    __syncthreads();
    int n = ccount < MAXCAND ? ccount : MAXCAND;
    float pg = g_p[b];
    const float* featb = &g_feat[b * NK3];

    for (int c = 0; c < n; c++) {
        int v = cand[c];
        float a = 0.0f, cs = 0.0f;
        if (v < NV) {
            const float* wv = W_vocab + (size_t)v * NK3;
            for (int k = tid; k < NK3; k += 256) a = fmaf(featb[k], wv[k], a);
        }
        for (int s = tid; s < NSRC; s += 256) {
            if (ext[b * NSRC + s] == v) cs += g_aw[b * NSRC + s];
        }
        a = warp_sum(a);
        cs = warp_sum(cs);
        if (lane == 0) { redA[wid] = a; redC[wid] = cs; }
        __syncthreads();
        if (tid == 0) {
            float A = 0.f, C = 0.f;
            for (int i = 0; i < 8; i++) { A += redA[i]; C += redC[i]; }
            float g = (v < NV) ? (A + b_vocab[v]) * (1.0f - pg) : 0.0f;
            cval[c] = g + pg * C;
        }
        __syncthreads();
    }

    if (tid == 0) {
        float best = -1e30f; int bi = 0;
        for (int c = 0; c < n; c++) {
            if (cval[c] > best || (cval[c] == best && cand[c] < bi)) { best = cval[c]; bi = cand[c]; }
        }
        if (pred_out) pred_out[b * NT + di] = (float)bi;
    }
}

// ---------------- host ----------------
extern "C" void kernel_launch(void* const* d_in, const int* in_sizes, int n_in,
                              void* d_out, int out_size) {
    const int*   dec     = (const int*)d_in[0];
    const int*   ext     = (const int*)d_in[1];
    const float* enc     = (const float*)d_in[2];
    const float* h0      = (const float*)d_in[3];
    const float* c0      = (const float*)d_in[4];
    const float* emb     = (const float*)d_in[5];
    const float* W_ih    = (const float*)d_in[6];
    const float* W_hh    = (const float*)d_in[7];
    const float* b_ih    = (const float*)d_in[8];
    const float* b_hh    = (const float*)d_in[9];
    const float* W_attn  = (const float*)d_in[10];
    const float* W_vocab = (const float*)d_in[11];
    const float* b_vocab = (const float*)d_in[12];
    const float* W_copy  = (const float*)d_in[13];
    const float* b_copy  = (const float*)d_in[14];

    float* out = (float*)d_out;
    const long long logp_elems = (long long)NB * NT * NVEXT;
    float* pred_out = (out_size > logp_elems) ? out + logp_elems : nullptr;

    k_init_state<<<(NB * NH + 255) / 256, 256>>>(h0, c0);
    k_transpose_small<<<(2048 * 512 + 255) / 256, 256>>>(W_ih, W_hh);
    k_transpose_vocab<<<dim3(VPAD / 32, NK3 / 32), dim3(32, 8)>>>(W_vocab);

    for (int di = 0; di < NT; di++) {
        k_gates<<<dim3(16, 2, 4), 128>>>(dec, emb, di);
        k_cell<<<(NB * NH + 255) / 256, 256>>>(b_ih, b_hh, di);
        k_q<<<dim3(NB, 4), 128>>>(W_attn);
        k_attn<<<NB, 256>>>(enc, W_copy, b_copy, di);
        k_vocab<<<dim3(126, 2), 128>>>(b_vocab, out, di);
        k_scatter<<<(NB * NSRC + 255) / 256, 256>>>(ext, out, di);
        k_logsm<<<NB, 256>>>(out, di);
        k_rescore<<<NB, 256>>>(W_vocab, b_vocab, ext, out, pred_out, di);
    }
}

// round 4
// speedup vs baseline: 8.0457x; 8.0457x over previous
#include <cuda_runtime.h>
#include <cuda_bf16.h>
#include <math.h>
#include <stdint.h>

// ---------------- problem constants ----------------
#define NB    32
#define NT    32
#define NH    512
#define NSRC  400
#define NV    32000
#define NVEXT 32050
#define NK3   1536
#define NG4   2048
#define ATTN_SCALE 0.04419417382415922f
#define RESCORE_MARGIN 1.5e-3f
#define MAXCAND 64
#define NROWS (NB * NT)

typedef unsigned long long ull;

// ---------------- device scratch ----------------
__device__ float g_WT_ih[512 * 2048];
__device__ float g_WT_hh[512 * 2048];
__device__ __nv_bfloat16 g_WB[(size_t)NV * NK3];        // W_vocab bf16 [v][k]
__device__ __nv_bfloat16 g_featB[(size_t)NROWS * NK3];  // feat bf16 [row][k]
__device__ float g_h[NB * NH];
__device__ float g_c[NB * NH];
__device__ float g_buf[NB * NT * NH];
__device__ float g_gpart[8 * NB * NG4];
__device__ float g_feat[(size_t)NROWS * NK3];
__device__ float g_aw[(size_t)NROWS * NSRC];
__device__ float g_p[NROWS];

// ---------------- helpers ----------------
__device__ __forceinline__ float warp_sum(float v) {
    #pragma unroll
    for (int o = 16; o; o >>= 1) v += __shfl_xor_sync(0xffffffffu, v, o);
    return v;
}
__device__ __forceinline__ float warp_max(float v) {
    #pragma unroll
    for (int o = 16; o; o >>= 1) v = fmaxf(v, __shfl_xor_sync(0xffffffffu, v, o));
    return v;
}
__device__ __forceinline__ float sigmoidf_(float x) { return 1.0f / (1.0f + expf(-x)); }

__device__ __forceinline__ uint32_t smem_u32(const void* p) {
    uint32_t a;
    asm("{ .reg .u64 t; cvta.to.shared.u64 t, %1; cvt.u32.u64 %0, t; }" : "=r"(a) : "l"(p));
    return a;
}
__device__ __forceinline__ void cp16(uint32_t s, const void* g) {
    asm volatile("cp.async.cg.shared.global [%0], [%1], 16;" :: "r"(s), "l"(g));
}
#define CP_COMMIT() asm volatile("cp.async.commit_group;" ::: "memory")
#define CP_WAIT1()  asm volatile("cp.async.wait_group 1;" ::: "memory")
#define CP_WAIT0()  asm volatile("cp.async.wait_group 0;" ::: "memory")

__device__ __forceinline__ void ldsm_x4(uint32_t& r0, uint32_t& r1, uint32_t& r2, uint32_t& r3, uint32_t a) {
    asm volatile("ldmatrix.sync.aligned.m8n8.x4.shared.b16 {%0,%1,%2,%3}, [%4];"
                 : "=r"(r0), "=r"(r1), "=r"(r2), "=r"(r3) : "r"(a));
}
__device__ __forceinline__ void ldsm_x2(uint32_t& r0, uint32_t& r1, uint32_t a) {
    asm volatile("ldmatrix.sync.aligned.m8n8.x2.shared.b16 {%0,%1}, [%2];"
                 : "=r"(r0), "=r"(r1) : "r"(a));
}
__device__ __forceinline__ void mma16816(float* d, const uint32_t* a, const uint32_t* b) {
    asm volatile("mma.sync.aligned.m16n8k16.row.col.f32.bf16.bf16.f32 "
                 "{%0,%1,%2,%3},{%4,%5,%6,%7},{%8,%9},{%0,%1,%2,%3};"
                 : "+f"(d[0]), "+f"(d[1]), "+f"(d[2]), "+f"(d[3])
                 : "r"(a[0]), "r"(a[1]), "r"(a[2]), "r"(a[3]), "r"(b[0]), "r"(b[1]));
}

// ---------------- init kernels ----------------
__global__ void k_init_state(const float* __restrict__ h0, const float* __restrict__ c0) {
    int i = blockIdx.x * 256 + threadIdx.x;
    if (i < NB * NH) { g_h[i] = h0[i]; g_c[i] = c0[i]; }
}
__global__ void k_transpose_small(const float* __restrict__ W_ih, const float* __restrict__ W_hh) {
    int i = blockIdx.x * 256 + threadIdx.x;
    if (i < 2048 * 512) {
        int j = i >> 9, k = i & 511;
        g_WT_ih[k * 2048 + j] = W_ih[i];
        g_WT_hh[k * 2048 + j] = W_hh[i];
    }
}
__global__ void k_wbconv(const float* __restrict__ W_vocab) {
    size_t i = ((size_t)blockIdx.x * 256 + threadIdx.x) * 4;
    if (i < (size_t)NV * NK3) {
        float4 v = *(const float4*)(W_vocab + i);
        __nv_bfloat162* d = (__nv_bfloat162*)(g_WB + i);
        d[0] = __floats2bfloat162_rn(v.x, v.y);
        d[1] = __floats2bfloat162_rn(v.z, v.w);
    }
}

// ---------------- recurrence: LSTM gates ----------------
__global__ void __launch_bounds__(128) k_gates(const int* __restrict__ dec,
                                               const float* __restrict__ emb, int di) {
    __shared__ float xs[128][16];
    int tid = threadIdx.x;
    int j   = blockIdx.x * 128 + tid;
    int b0  = blockIdx.y * 16;
    int kq  = blockIdx.z;
    int koff = (kq & 3) * 128;

    for (int idx = tid; idx < 128 * 16; idx += 128) {
        int kk = idx >> 4, bb = idx & 15;
        int b = b0 + bb;
        float v;
        if (kq < 4) {
            int tok = dec[b * (NT + 1) + di];
            if (tok >= NV) tok = 1;
            v = emb[tok * NH + koff + kk];
        } else {
            v = g_h[b * NH + koff + kk];
        }
        xs[kk][bb] = v;
    }
    __syncthreads();

    const float* WT = (kq < 4) ? g_WT_ih : g_WT_hh;
    const float* wp = &WT[(size_t)koff * NG4 + j];
    float acc[16];
    #pragma unroll
    for (int bb = 0; bb < 16; bb++) acc[bb] = 0.0f;

    #pragma unroll 8
    for (int kk = 0; kk < 128; kk++) {
        float w = wp[(size_t)kk * NG4];
        #pragma unroll
        for (int bb = 0; bb < 16; bb++) acc[bb] = fmaf(w, xs[kk][bb], acc[bb]);
    }
    #pragma unroll
    for (int bb = 0; bb < 16; bb++)
        g_gpart[((kq * NB) + b0 + bb) * NG4 + j] = acc[bb];
}

// ---------------- recurrence: cell update ----------------
__global__ void k_cell(const float* __restrict__ b_ih, const float* __restrict__ b_hh, int di) {
    int idx = blockIdx.x * 256 + threadIdx.x;
    if (idx >= NB * NH) return;
    int b = idx >> 9, hh = idx & 511;
    float vi = b_ih[hh]        + b_hh[hh];
    float vf = b_ih[512 + hh]  + b_hh[512 + hh];
    float vg = b_ih[1024 + hh] + b_hh[1024 + hh];
    float vo = b_ih[1536 + hh] + b_hh[1536 + hh];
    #pragma unroll
    for (int kq = 0; kq < 8; kq++) {
        const float* gp = &g_gpart[((kq * NB) + b) * NG4];
        vi += gp[hh]; vf += gp[512 + hh]; vg += gp[1024 + hh]; vo += gp[1536 + hh];
    }
    float c = sigmoidf_(vf) * g_c[idx] + sigmoidf_(vi) * tanhf(vg);
    float h = sigmoidf_(vo) * tanhf(c);
    g_c[idx] = c;
    g_h[idx] = h;
    g_buf[b * (NT * NH) + di * NH + hh] = h;
}

// ---------------- recurrence: fused q + attentions + feat + copy gate ----------------
__global__ void __launch_bounds__(512) k_attn(const float* __restrict__ enc,
                                              const float* __restrict__ W_attn,
                                              const float* __restrict__ W_copy,
                                              const float* __restrict__ b_copy, int di) {
    __shared__ float hs[512], qs[512], sc[NSRC], ss[32], sws[32], red[16];
    int b = blockIdx.x, tid = threadIdx.x;
    int lane = tid & 31, wid = tid >> 5;
    int row = b * NT + di;
    const float* encb = enc + (size_t)b * NSRC * NH;
    const float* bufb = &g_buf[b * (NT * NH)];

    hs[tid] = g_h[b * NH + tid];
    __syncthreads();

    // q = h @ W_attn   (q[e] = sum_h hs[h] * W_attn[h*NH+e])
    float qa = 0.0f;
    #pragma unroll 8
    for (int h = 0; h < 512; h++) qa = fmaf(hs[h], W_attn[h * NH + tid], qa);
    qs[tid] = qa;
    __syncthreads();

    // encoder scores
    for (int s = wid; s < NSRC; s += 16) {
        float a = 0.0f;
        #pragma unroll
        for (int i = 0; i < 16; i++)
            a = fmaf(qs[lane + 32 * i], encb[(size_t)s * NH + lane + 32 * i], a);
        a = warp_sum(a);
        if (lane == 0) sc[s] = a * ATTN_SCALE;
    }
    __syncthreads();

    // softmax over 400
    float m = (tid < NSRC) ? sc[tid] : -1e30f;
    m = warp_max(m);
    if (lane == 0) red[wid] = m;
    __syncthreads();
    if (tid == 0) { float t = red[0]; for (int i = 1; i < 16; i++) t = fmaxf(t, red[i]); red[0] = t; }
    __syncthreads();
    float gm = red[0];
    __syncthreads();
    float ls = 0.0f;
    if (tid < NSRC) { float e = expf(sc[tid] - gm); sc[tid] = e; ls = e; }
    ls = warp_sum(ls);
    if (lane == 0) red[wid] = ls;
    __syncthreads();
    if (tid == 0) { float t = 0.f; for (int i = 0; i < 16; i++) t += red[i]; red[0] = t; }
    __syncthreads();
    float inv = 1.0f / red[0];
    if (tid < NSRC) { float a = sc[tid] * inv; sc[tid] = a; g_aw[(size_t)row * NSRC + tid] = a; }

    // intra-decoder scores + softmax
    if (di > 0) {
        for (int t = wid; t < di; t += 16) {
            float a = 0.0f;
            #pragma unroll
            for (int i = 0; i < 16; i++)
                a = fmaf(hs[lane + 32 * i], bufb[t * NH + lane + 32 * i], a);
            a = warp_sum(a);
            if (lane == 0) ss[t] = a * ATTN_SCALE;
        }
        __syncthreads();
        if (tid < 32) {
            float v = (tid < di) ? ss[tid] : -1e30f;
            float mm = warp_max(v);
            float e = (tid < di) ? expf(v - mm) : 0.0f;
            float s = warp_sum(e);
            sws[tid] = (tid < di) ? e / s : 0.0f;
        }
    } else {
        if (tid < 32) sws[tid] = 0.0f;
    }
    __syncthreads();

    // contexts + feat + copy-gate contribution (thread = h index)
    int h = tid;
    float ed = 0.0f;
    #pragma unroll 8
    for (int s = 0; s < NSRC; s++) ed = fmaf(sc[s], encb[(size_t)s * NH + h], ed);
    float ds = 0.0f;
    for (int t = 0; t < di; t++) ds = fmaf(sws[t], bufb[t * NH + h], ds);
    float hv = hs[h];

    float* f = &g_feat[(size_t)row * NK3];
    f[h] = hv; f[512 + h] = ed; f[1024 + h] = ds;
    __nv_bfloat16* fb = &g_featB[(size_t)row * NK3];
    fb[h] = __float2bfloat16(hv);
    fb[512 + h] = __float2bfloat16(ed);
    fb[1024 + h] = __float2bfloat16(ds);

    float pc = hv * W_copy[h] + ed * W_copy[512 + h] + ds * W_copy[1024 + h];
    pc = warp_sum(pc);
    if (lane == 0) red[wid] = pc;
    __syncthreads();
    if (tid == 0) {
        float t = 0.f;
        for (int i = 0; i < 16; i++) t += red[i];
        g_p[row] = sigmoidf_(t + b_copy[0]);
    }
}

// ---------------- batched vocab GEMM: mma.sync bf16 ----------------
// 128x128 tile / CTA, BK=64, double-buffered cp.async. 8 warps: 2(m) x 4(n), 64x32 each.
#define BK      64
#define ROWB    144                      // (64+8) bf16 row stride in bytes
#define ATILE   (128 * ROWB)             // 18432 B
#define STAGEB  (2 * ATILE)              // 36864 B per buffer
#define GSMEM   (2 * STAGEB)             // 73728 B

__global__ void __launch_bounds__(256) k_gemm(const float* __restrict__ b_vocab,
                                              float* __restrict__ out) {
    extern __shared__ char dsm[];
    int tid = threadIdx.x;
    int lane = tid & 31, wid = tid >> 5;
    int wm = wid & 1, wn = wid >> 1;
    int m0 = blockIdx.x * 128;
    int n0 = blockIdx.y * 128;
    uint32_t sbase = smem_u32(dsm);

    float d[4][4][4];
    #pragma unroll
    for (int i = 0; i < 4; i++)
        #pragma unroll
        for (int j = 0; j < 4; j++)
            #pragma unroll
            for (int r = 0; r < 4; r++) d[i][j][r] = 0.0f;

    // stage loader: 2048 x 16B (A: 128 rows x 64k, B: 128 rows x 64k)
    auto load_stage = [&](int stage, int buf) {
        int k0 = stage * BK;
        uint32_t dst0 = sbase + buf * STAGEB;
        #pragma unroll
        for (int it = 0; it < 8; it++) {
            int i = it * 256 + tid;
            int half = i >> 10;
            int idx  = i & 1023;
            int r = idx >> 3, q = idx & 7;
            const __nv_bfloat16* src = half
                ? (g_WB    + (size_t)(n0 + r) * NK3 + k0 + q * 8)
                : (g_featB + (size_t)(m0 + r) * NK3 + k0 + q * 8);
            cp16(dst0 + half * ATILE + r * ROWB + q * 16, src);
        }
    };

    load_stage(0, 0); CP_COMMIT();
    load_stage(1, 1); CP_COMMIT();

    // per-lane ldmatrix base addresses (within a buffer)
    uint32_t a_off = (uint32_t)((wm * 64 + (lane & 15)) * ROWB + (lane >> 4) * 16);
    int lb = lane & 15;
    uint32_t b_off = (uint32_t)(ATILE + (wn * 32 + (lb & 7)) * ROWB + ((lb >> 3) & 1) * 16);

    for (int s = 0; s < 24; s++) {
        if (s == 23) { CP_WAIT0(); } else { CP_WAIT1(); }
        __syncthreads();
        int buf = s & 1;
        uint32_t base = sbase + buf * STAGEB;

        #pragma unroll
        for (int ks = 0; ks < 4; ks++) {
            uint32_t a[4][4], bfr[4][2];
            #pragma unroll
            for (int i = 0; i < 4; i++)
                ldsm_x4(a[i][0], a[i][1], a[i][2], a[i][3],
                        base + a_off + i * (16 * ROWB) + ks * 32);
            #pragma unroll
            for (int j = 0; j < 4; j++)
                ldsm_x2(bfr[j][0], bfr[j][1],
                        base + b_off + j * (8 * ROWB) + ks * 32);
            #pragma unroll
            for (int i = 0; i < 4; i++)
                #pragma unroll
                for (int j = 0; j < 4; j++)
                    mma16816(d[i][j], a[i], bfr[j]);
        }
        __syncthreads();
        if (s + 2 < 24) { load_stage(s + 2, buf); CP_COMMIT(); }
    }

    // epilogue: (acc + bias) * (1 - p) -> out
    #pragma unroll
    for (int i = 0; i < 4; i++) {
        int r0 = m0 + wm * 64 + 16 * i + (lane >> 2);
        float pm0 = 1.0f - g_p[r0];
        float pm1 = 1.0f - g_p[r0 + 8];
        float* o0 = out + (size_t)r0 * NVEXT;
        float* o1 = out + (size_t)(r0 + 8) * NVEXT;
        #pragma unroll
        for (int j = 0; j < 4; j++) {
            int c = n0 + wn * 32 + 8 * j + (lane & 3) * 2;
            float bv0 = b_vocab[c], bv1 = b_vocab[c + 1];
            o0[c]     = (d[i][j][0] + bv0) * pm0;
            o0[c + 1] = (d[i][j][1] + bv1) * pm0;
            o1[c]     = (d[i][j][2] + bv0) * pm1;
            o1[c + 1] = (d[i][j][3] + bv1) * pm1;
        }
    }
}

// ---------------- batched tail ----------------
__global__ void k_zeroext(float* __restrict__ out) {
    int idx = blockIdx.x * 256 + threadIdx.x;
    if (idx < NROWS * (NVEXT - NV)) {
        int r = idx / (NVEXT - NV), v = NV + idx % (NVEXT - NV);
        out[(size_t)r * NVEXT + v] = 0.0f;
    }
}
__global__ void k_scatter(const int* __restrict__ ext, float* __restrict__ out) {
    int idx = blockIdx.x * 256 + threadIdx.x;
    if (idx >= NROWS * NSRC) return;
    int r = idx / NSRC, s = idx - r * NSRC;
    int b = r >> 5;
    float add = g_p[r] * g_aw[(size_t)r * NSRC + s];
    atomicAdd(out + (size_t)r * NVEXT + ext[b * NSRC + s], add);
}
__global__ void k_logsm(float* __restrict__ out) {
    __shared__ float sred[256];
    int r = blockIdx.x, tid = threadIdx.x;
    float* row = out + (size_t)r * NVEXT;
    float m = -1e30f;
    for (int v = tid; v < NVEXT; v += 256) m = fmaxf(m, row[v]);
    sred[tid] = m;
    __syncthreads();
    for (int s = 128; s > 0; s >>= 1) { if (tid < s) sred[tid] = fmaxf(sred[tid], sred[tid + s]); __syncthreads(); }
    float gm = sred[0];
    __syncthreads();
    float ls = 0.0f;
    for (int v = tid; v < NVEXT; v += 256) ls += expf(row[v] - gm);
    sred[tid] = ls;
    __syncthreads();
    for (int s = 128; s > 0; s >>= 1) { if (tid < s) sred[tid] += sred[tid + s]; __syncthreads(); }
    float lz = gm + logf(sred[0]);
    for (int v = tid; v < NVEXT; v += 256) row[v] = row[v] - lz;
}
// exact-fp32 rescore of near-max candidates -> argmax
__global__ void k_rescore(const float* __restrict__ W_vocab,
                          const float* __restrict__ b_vocab,
                          const int* __restrict__ ext,
                          const float* __restrict__ out,
                          float* __restrict__ pred_out) {
    __shared__ float redA[8], redC[8], sred[256];
    __shared__ int   cand[MAXCAND];
    __shared__ float cval[MAXCAND];
    __shared__ int   ccount;
    int r = blockIdx.x, tid = threadIdx.x;
    int lane = tid & 31, wid = tid >> 5;
    int b = r >> 5;
    const float* row = out + (size_t)r * NVEXT;

    float m = -1e30f;
    for (int v = tid; v < NVEXT; v += 256) m = fmaxf(m, row[v]);
    sred[tid] = m;
    __syncthreads();
    for (int s = 128; s > 0; s >>= 1) { if (tid < s) sred[tid] = fmaxf(sred[tid], sred[tid + s]); __syncthreads(); }
    float thr = sred[0] - RESCORE_MARGIN;
    if (tid == 0) ccount = 0;
    __syncthreads();
    for (int v = tid; v < NVEXT; v += 256) {
        if (row[v] >= thr) {
            int p = atomicAdd(&ccount, 1);
            if (p < MAXCAND) cand[p] = v;
        }
    }
    __syncthreads();
    int n = ccount < MAXCAND ? ccount : MAXCAND;
    float pg = g_p[r];
    const float* featb = &g_feat[(size_t)r * NK3];

    for (int c = 0; c < n; c++) {
        int v = cand[c];
        float a = 0.0f, cs = 0.0f;
        if (v < NV) {
            const float* wv = W_vocab + (size_t)v * NK3;
            for (int k = tid; k < NK3; k += 256) a = fmaf(featb[k], wv[k], a);
        }
        for (int s = tid; s < NSRC; s += 256)
            if (ext[b * NSRC + s] == v) cs += g_aw[(size_t)r * NSRC + s];
        a = warp_sum(a); cs = warp_sum(cs);
        if (lane == 0) { redA[wid] = a; redC[wid] = cs; }
        __syncthreads();
        if (tid == 0) {
            float A = 0.f, C = 0.f;
            for (int i = 0; i < 8; i++) { A += redA[i]; C += redC[i]; }
            float g = (v < NV) ? (A + b_vocab[v]) * (1.0f - pg) : 0.0f;
            cval[c] = g + pg * C;
        }
        __syncthreads();
    }
    if (tid == 0) {
        float best = -1e30f; int bi = 0;
        for (int c = 0; c < n; c++)
            if (cval[c] > best || (cval[c] == best && cand[c] < bi)) { best = cval[c]; bi = cand[c]; }
        if (pred_out) pred_out[r] = (float)bi;
    }
}

// ---------------- host ----------------
extern "C" void kernel_launch(void* const* d_in, const int* in_sizes, int n_in,
                              void* d_out, int out_size) {
    const int*   dec     = (const int*)d_in[0];
    const int*   ext     = (const int*)d_in[1];
    const float* enc     = (const float*)d_in[2];
    const float* h0      = (const float*)d_in[3];
    const float* c0      = (const float*)d_in[4];
    const float* emb     = (const float*)d_in[5];
    const float* W_ih    = (const float*)d_in[6];
    const float* W_hh    = (const float*)d_in[7];
    const float* b_ih    = (const float*)d_in[8];
    const float* b_hh    = (const float*)d_in[9];
    const float* W_attn  = (const float*)d_in[10];
    const float* W_vocab = (const float*)d_in[11];
    const float* b_vocab = (const float*)d_in[12];
    const float* W_copy  = (const float*)d_in[13];
    const float* b_copy  = (const float*)d_in[14];

    float* out = (float*)d_out;
    const long long logp_elems = (long long)NROWS * NVEXT;
    float* pred_out = (out_size > logp_elems) ? out + logp_elems : nullptr;

    cudaFuncSetAttribute(k_gemm, cudaFuncAttributeMaxDynamicSharedMemorySize, GSMEM);

    k_init_state<<<(NB * NH + 255) / 256, 256>>>(h0, c0);
    k_transpose_small<<<(2048 * 512 + 255) / 256, 256>>>(W_ih, W_hh);
    k_wbconv<<<(int)(((size_t)NV * NK3 / 4 + 255) / 256), 256>>>(W_vocab);

    for (int di = 0; di < NT; di++) {
        k_gates<<<dim3(16, 2, 8), 128>>>(dec, emb, di);
        k_cell<<<(NB * NH + 255) / 256, 256>>>(b_ih, b_hh, di);
        k_attn<<<NB, 512>>>(enc, W_attn, W_copy, b_copy, di);
    }

    k_gemm<<<dim3(8, 250), 256, GSMEM>>>(b_vocab, out);
    k_zeroext<<<(NROWS * (NVEXT - NV) + 255) / 256, 256>>>(out);
    k_scatter<<<(NROWS * NSRC + 255) / 256, 256>>>(ext, out);
    k_logsm<<<NROWS, 256>>>(out);
    k_rescore<<<NROWS, 256>>>(W_vocab, b_vocab, ext, out, pred_out);
}